// round 1
// baseline (speedup 1.0000x reference)
#include <cuda_runtime.h>
#include <math.h>

#define T_TOK 8192
#define D_DIM 1024
#define E_EXP 8
#define TOPK  2
#define FFD   2048
#define W1S   (FFD * E_EXP)   /* 16384: row stride of w1 */
#define NPAIR (T_TOK * TOPK)  /* 16384 */
#define BM 128
#define BN 64
#define BK 16
#define NT_ROW 136            /* ceil((16384 + 8*127)/128) capacity tiles */
#define CAP (NT_ROW * BM)     /* 17408 padded pair slots */

// ---------------- static device scratch (no runtime allocation) ----------------
__device__ float g_H[(size_t)CAP * FFD];     // gelu(x@W1) per (token,expert) pair slot
__device__ float g_O[(size_t)CAP * D_DIM];   // (H@W2) per pair slot (unweighted)
__device__ int   g_pair_token[CAP];          // token index per slot, -1 = padding
__device__ int   g_pair_pos[NPAIR];          // slot for (t, k)
__device__ int   g_sel[NPAIR];               // selected expert per (t, k)
__device__ float g_topw[NPAIR];              // normalized top-k weight per (t, k)
__device__ int   g_count[E_EXP];
__device__ int   g_cursor[E_EXP];
__device__ int   g_off[E_EXP + 1];           // padded segment offsets
__device__ float g_z_acc;                    // sum of lse^2
__device__ float g_p_acc[E_EXP];             // sum of softmax probs per expert

__device__ __forceinline__ float gelu_exact(float v) {
    return 0.5f * v * (1.0f + erff(v * 0.70710678118654752440f));
}

// ---------------- init ----------------
__global__ void k_init() {
    int i = blockIdx.x * 256 + threadIdx.x;
    if (i < CAP) g_pair_token[i] = -1;
    if (i < E_EXP) { g_count[i] = 0; g_cursor[i] = 0; g_p_acc[i] = 0.0f; }
    if (i == 0) g_z_acc = 0.0f;
}

// ---------------- router: logits, softmax, top-2, loss partials ----------------
__global__ __launch_bounds__(256) void k_router(const float* __restrict__ x,
                                                const float* __restrict__ rw) {
    __shared__ float xs[D_DIM];
    __shared__ float logits[E_EXP];
    int t = blockIdx.x;
    const float* xr = x + (size_t)t * D_DIM;
    for (int i = threadIdx.x; i < D_DIM; i += 256) xs[i] = xr[i];
    __syncthreads();
    int w = threadIdx.x >> 5, lane = threadIdx.x & 31;
    // 8 warps, warp w computes expert w's logit
    float s = 0.0f;
    const float* we = rw + (size_t)w * D_DIM;
    for (int i = lane; i < D_DIM; i += 32) s += xs[i] * we[i];
    for (int o = 16; o; o >>= 1) s += __shfl_xor_sync(0xFFFFFFFFu, s, o);
    if (lane == 0) logits[w] = s;
    __syncthreads();
    if (threadIdx.x == 0) {
        float mx = logits[0];
        for (int e = 1; e < E_EXP; e++) mx = fmaxf(mx, logits[e]);
        float p[E_EXP]; float se = 0.0f;
        for (int e = 0; e < E_EXP; e++) { p[e] = expf(logits[e] - mx); se += p[e]; }
        float inv = 1.0f / se;
        for (int e = 0; e < E_EXP; e++) p[e] *= inv;
        float lse = mx + logf(se);
        atomicAdd(&g_z_acc, lse * lse);
        for (int e = 0; e < E_EXP; e++) atomicAdd(&g_p_acc[e], p[e]);
        // top-2 (ties -> lowest index, matching lax.top_k)
        int i0 = 0;
        for (int e = 1; e < E_EXP; e++) if (p[e] > p[i0]) i0 = e;
        int i1 = -1;
        for (int e = 0; e < E_EXP; e++) {
            if (e == i0) continue;
            if (i1 < 0 || p[e] > p[i1]) i1 = e;
        }
        float s2 = p[i0] + p[i1];
        g_sel[t * 2 + 0] = i0; g_sel[t * 2 + 1] = i1;
        g_topw[t * 2 + 0] = p[i0] / s2; g_topw[t * 2 + 1] = p[i1] / s2;
        atomicAdd(&g_count[i0], 1); atomicAdd(&g_count[i1], 1);
    }
}

// ---------------- scan: padded per-expert offsets ----------------
__global__ void k_scan() {
    if (threadIdx.x == 0) {
        int off = 0;
        for (int e = 0; e < E_EXP; e++) {
            g_off[e] = off;
            off += ((g_count[e] + BM - 1) / BM) * BM;
        }
        g_off[E_EXP] = off;
    }
}

// ---------------- scatter tokens into expert segments ----------------
__global__ void k_scatter() {
    int t = blockIdx.x * 256 + threadIdx.x;
    if (t >= T_TOK) return;
    #pragma unroll
    for (int k = 0; k < TOPK; k++) {
        int e = g_sel[t * 2 + k];
        int pos = atomicAdd(&g_cursor[e], 1);
        int slot = g_off[e] + pos;
        g_pair_token[slot] = t;
        g_pair_pos[t * 2 + k] = slot;
    }
}

// ---------------- GEMM1: H[slot] = gelu(x[tok] @ W1_e) ----------------
__global__ __launch_bounds__(256) void k_gemm1(const float* __restrict__ x,
                                               const float* __restrict__ w1) {
    __shared__ float As[BK][BM];
    __shared__ float Bs[BK][BN];
    __shared__ int toks[BM];
    int row0 = blockIdx.x * BM;
    if (row0 >= g_off[E_EXP]) return;
    int e = 0;
    while (row0 >= g_off[e + 1]) e++;
    int nbase = blockIdx.y * BN;
    int tid = threadIdx.x;
    if (tid < BM) toks[tid] = g_pair_token[row0 + tid];
    __syncthreads();

    int am = tid >> 1;
    int aq = (tid & 1) * 2;            // float4 quad index within 16-float chunk
    int atok = toks[am];
    const float4* xrow = (atok >= 0) ? (const float4*)(x + (size_t)atok * D_DIM)
                                     : (const float4*)nullptr;
    int bk  = tid >> 4;                // 0..15
    int bn4 = (tid & 15) << 2;         // 0,4,..,60
    const float* bbase = w1 + (size_t)e * FFD + nbase + bn4;
    int ty = tid >> 4, tx = tid & 15;

    float acc[8][4];
    #pragma unroll
    for (int i = 0; i < 8; i++)
        #pragma unroll
        for (int j = 0; j < 4; j++) acc[i][j] = 0.0f;

    for (int k0 = 0; k0 < D_DIM; k0 += BK) {
        float4 a0 = make_float4(0.f,0.f,0.f,0.f), a1 = a0;
        if (xrow) { a0 = xrow[(k0 >> 2) + aq]; a1 = xrow[(k0 >> 2) + aq + 1]; }
        float4 b = *(const float4*)(bbase + (size_t)(k0 + bk) * W1S);
        __syncthreads();
        As[aq*4+0][am] = a0.x; As[aq*4+1][am] = a0.y;
        As[aq*4+2][am] = a0.z; As[aq*4+3][am] = a0.w;
        As[aq*4+4][am] = a1.x; As[aq*4+5][am] = a1.y;
        As[aq*4+6][am] = a1.z; As[aq*4+7][am] = a1.w;
        *(float4*)&Bs[bk][bn4] = b;
        __syncthreads();
        #pragma unroll
        for (int kk = 0; kk < BK; kk++) {
            float a[8], bb[4];
            *(float4*)&a[0] = *(const float4*)&As[kk][ty * 8];
            *(float4*)&a[4] = *(const float4*)&As[kk][ty * 8 + 4];
            *(float4*)&bb[0] = *(const float4*)&Bs[kk][tx * 4];
            #pragma unroll
            for (int i = 0; i < 8; i++)
                #pragma unroll
                for (int j = 0; j < 4; j++) acc[i][j] = fmaf(a[i], bb[j], acc[i][j]);
        }
    }
    // epilogue: exact gelu, store H
    #pragma unroll
    for (int i = 0; i < 8; i++) {
        int slot = row0 + ty * 8 + i;
        float4 v;
        v.x = gelu_exact(acc[i][0]); v.y = gelu_exact(acc[i][1]);
        v.z = gelu_exact(acc[i][2]); v.w = gelu_exact(acc[i][3]);
        *(float4*)&g_H[(size_t)slot * FFD + nbase + tx * 4] = v;
    }
}

// ---------------- GEMM2: O[slot] = H[slot] @ W2_e ----------------
__global__ __launch_bounds__(256) void k_gemm2(const float* __restrict__ w2) {
    __shared__ float As[BK][BM];
    __shared__ float Bs[BK][BN];
    int row0 = blockIdx.x * BM;
    if (row0 >= g_off[E_EXP]) return;
    int e = 0;
    while (row0 >= g_off[e + 1]) e++;
    int nbase = blockIdx.y * BN;
    int tid = threadIdx.x;

    int am = tid >> 1;
    int aq = (tid & 1) * 2;
    const float4* hrow = (const float4*)(g_H + (size_t)(row0 + am) * FFD);
    int bk  = tid >> 4;
    int bn4 = (tid & 15) << 2;
    const float* bbase = w2 + (size_t)e * FFD * D_DIM + nbase + bn4;
    int ty = tid >> 4, tx = tid & 15;

    float acc[8][4];
    #pragma unroll
    for (int i = 0; i < 8; i++)
        #pragma unroll
        for (int j = 0; j < 4; j++) acc[i][j] = 0.0f;

    for (int k0 = 0; k0 < FFD; k0 += BK) {
        float4 a0 = hrow[(k0 >> 2) + aq];
        float4 a1 = hrow[(k0 >> 2) + aq + 1];
        float4 b = *(const float4*)(bbase + (size_t)(k0 + bk) * D_DIM);
        __syncthreads();
        As[aq*4+0][am] = a0.x; As[aq*4+1][am] = a0.y;
        As[aq*4+2][am] = a0.z; As[aq*4+3][am] = a0.w;
        As[aq*4+4][am] = a1.x; As[aq*4+5][am] = a1.y;
        As[aq*4+6][am] = a1.z; As[aq*4+7][am] = a1.w;
        *(float4*)&Bs[bk][bn4] = b;
        __syncthreads();
        #pragma unroll
        for (int kk = 0; kk < BK; kk++) {
            float a[8], bb[4];
            *(float4*)&a[0] = *(const float4*)&As[kk][ty * 8];
            *(float4*)&a[4] = *(const float4*)&As[kk][ty * 8 + 4];
            *(float4*)&bb[0] = *(const float4*)&Bs[kk][tx * 4];
            #pragma unroll
            for (int i = 0; i < 8; i++)
                #pragma unroll
                for (int j = 0; j < 4; j++) acc[i][j] = fmaf(a[i], bb[j], acc[i][j]);
        }
    }
    #pragma unroll
    for (int i = 0; i < 8; i++) {
        int slot = row0 + ty * 8 + i;
        float4 v = make_float4(acc[i][0], acc[i][1], acc[i][2], acc[i][3]);
        *(float4*)&g_O[(size_t)slot * D_DIM + nbase + tx * 4] = v;
    }
}

// ---------------- combine: out[t] = w0*O[p0] + w1*O[p1] ----------------
__global__ void k_combine(float* __restrict__ out) {
    int i = blockIdx.x * 256 + threadIdx.x;      // float4 index
    const int NQ = T_TOK * D_DIM / 4;
    if (i >= NQ) return;
    int t  = i / (D_DIM / 4);
    int d4 = i % (D_DIM / 4);
    int p0 = g_pair_pos[t * 2 + 0], p1 = g_pair_pos[t * 2 + 1];
    float w0 = g_topw[t * 2 + 0],  w1 = g_topw[t * 2 + 1];
    float4 o0 = *(const float4*)&g_O[(size_t)p0 * D_DIM + d4 * 4];
    float4 o1 = *(const float4*)&g_O[(size_t)p1 * D_DIM + d4 * 4];
    float4 r;
    r.x = w0 * o0.x + w1 * o1.x;
    r.y = w0 * o0.y + w1 * o1.y;
    r.z = w0 * o0.z + w1 * o1.z;
    r.w = w0 * o0.w + w1 * o1.w;
    ((float4*)out)[i] = r;
}

// ---------------- final scalars ----------------
__global__ void k_final(float* __restrict__ out, int out_size) {
    if (threadIdx.x == 0 && out_size >= T_TOK * D_DIM + 2) {
        float z = g_z_acc / (float)T_TOK;
        float lb = 0.0f;
        for (int e = 0; e < E_EXP; e++) {
            float f_i = (float)g_count[e] / (float)(T_TOK * TOPK);
            float p_i = g_p_acc[e] / (float)T_TOK;
            lb += f_i * p_i;
        }
        lb *= (float)E_EXP;
        out[T_TOK * D_DIM + 0] = z;
        out[T_TOK * D_DIM + 1] = lb;
    }
}

extern "C" void kernel_launch(void* const* d_in, const int* in_sizes, int n_in,
                              void* d_out, int out_size) {
    const float* x  = (const float*)d_in[0];
    const float* rw = (const float*)d_in[1];
    const float* w1 = (const float*)d_in[2];
    const float* w2 = (const float*)d_in[3];
    float* out = (float*)d_out;

    k_init<<<(CAP + 255) / 256, 256>>>();
    k_router<<<T_TOK, 256>>>(x, rw);
    k_scan<<<1, 32>>>();
    k_scatter<<<(T_TOK + 255) / 256, 256>>>();
    dim3 g1(NT_ROW, FFD / BN);
    k_gemm1<<<g1, 256>>>(x, w1);
    dim3 g2(NT_ROW, D_DIM / BN);
    k_gemm2<<<g2, 256>>>(w2);
    k_combine<<<(T_TOK * D_DIM / 4 + 255) / 256, 256>>>(out);
    k_final<<<1, 32>>>(out, out_size);
}

// round 9
// speedup vs baseline: 1.5105x; 1.5105x over previous
#include <cuda_runtime.h>
#include <cuda_bf16.h>
#include <math.h>
#include <stdint.h>

typedef __nv_bfloat16 bf16;

#define T_TOK 8192
#define D_DIM 1024
#define E_EXP 8
#define TOPK  2
#define FFD   2048
#define W1S   (FFD * E_EXP)
#define NPAIR (T_TOK * TOPK)
#define BM 128
#define NT_ROW 136
#define CAP (NT_ROW * BM)

// ---------------- static device scratch ----------------
__device__ __align__(16) bf16  g_Hhi[(size_t)CAP * FFD];
__device__ __align__(16) bf16  g_Hlo[(size_t)CAP * FFD];
__device__ __align__(16) float g_O[(size_t)CAP * D_DIM];
__device__ int   g_pair_token[CAP];
__device__ int   g_pair_pos[NPAIR];
__device__ int   g_sel[NPAIR];
__device__ float g_topw[NPAIR];
__device__ int   g_count[E_EXP];
__device__ int   g_cursor[E_EXP];
__device__ int   g_off[E_EXP + 1];
__device__ float g_z_acc;
__device__ float g_p_acc[E_EXP];

__device__ __forceinline__ float gelu_exact(float v) {
    return 0.5f * v * (1.0f + erff(v * 0.70710678118654752440f));
}
__device__ __forceinline__ uint32_t pack2(bf16 a, bf16 b) {
    return ((uint32_t)__bfloat16_as_ushort(b) << 16) | (uint32_t)__bfloat16_as_ushort(a);
}
__device__ __forceinline__ void split1(float f, bf16& h, bf16& l) {
    h = __float2bfloat16(f);
    l = __float2bfloat16(f - __bfloat162float(h));
}
__device__ __forceinline__ void mma16816(float* d, const uint32_t* a, const uint32_t* b) {
    asm volatile("mma.sync.aligned.m16n8k16.row.col.f32.bf16.bf16.f32 "
                 "{%0,%1,%2,%3}, {%4,%5,%6,%7}, {%8,%9}, {%0,%1,%2,%3};"
                 : "+f"(d[0]), "+f"(d[1]), "+f"(d[2]), "+f"(d[3])
                 : "r"(a[0]), "r"(a[1]), "r"(a[2]), "r"(a[3]), "r"(b[0]), "r"(b[1]));
}

// ---------------- init ----------------
__global__ void k_init() {
    int i = blockIdx.x * 256 + threadIdx.x;
    if (i < CAP) g_pair_token[i] = -1;
    if (i < E_EXP) { g_count[i] = 0; g_cursor[i] = 0; g_p_acc[i] = 0.0f; }
    if (i == 0) g_z_acc = 0.0f;
}

// ---------------- router ----------------
__global__ __launch_bounds__(256) void k_router(const float* __restrict__ x,
                                                const float* __restrict__ rw) {
    __shared__ float xs[D_DIM];
    __shared__ float logits[E_EXP];
    int t = blockIdx.x;
    const float* xr = x + (size_t)t * D_DIM;
    for (int i = threadIdx.x; i < D_DIM; i += 256) xs[i] = xr[i];
    __syncthreads();
    int w = threadIdx.x >> 5, lane = threadIdx.x & 31;
    float s = 0.0f;
    const float* we = rw + (size_t)w * D_DIM;
    for (int i = lane; i < D_DIM; i += 32) s += xs[i] * we[i];
    for (int o = 16; o; o >>= 1) s += __shfl_xor_sync(0xFFFFFFFFu, s, o);
    if (lane == 0) logits[w] = s;
    __syncthreads();
    if (threadIdx.x == 0) {
        float mx = logits[0];
        for (int e = 1; e < E_EXP; e++) mx = fmaxf(mx, logits[e]);
        float p[E_EXP]; float se = 0.0f;
        for (int e = 0; e < E_EXP; e++) { p[e] = expf(logits[e] - mx); se += p[e]; }
        float inv = 1.0f / se;
        for (int e = 0; e < E_EXP; e++) p[e] *= inv;
        float lse = mx + logf(se);
        atomicAdd(&g_z_acc, lse * lse);
        for (int e = 0; e < E_EXP; e++) atomicAdd(&g_p_acc[e], p[e]);
        int i0 = 0;
        for (int e = 1; e < E_EXP; e++) if (p[e] > p[i0]) i0 = e;
        int i1 = -1;
        for (int e = 0; e < E_EXP; e++) {
            if (e == i0) continue;
            if (i1 < 0 || p[e] > p[i1]) i1 = e;
        }
        float s2 = p[i0] + p[i1];
        g_sel[t * 2 + 0] = i0; g_sel[t * 2 + 1] = i1;
        g_topw[t * 2 + 0] = p[i0] / s2; g_topw[t * 2 + 1] = p[i1] / s2;
        atomicAdd(&g_count[i0], 1); atomicAdd(&g_count[i1], 1);
    }
}

__global__ void k_scan() {
    if (threadIdx.x == 0) {
        int off = 0;
        for (int e = 0; e < E_EXP; e++) {
            g_off[e] = off;
            off += ((g_count[e] + BM - 1) / BM) * BM;
        }
        g_off[E_EXP] = off;
    }
}

__global__ void k_scatter() {
    int t = blockIdx.x * 256 + threadIdx.x;
    if (t >= T_TOK) return;
    #pragma unroll
    for (int k = 0; k < TOPK; k++) {
        int e = g_sel[t * 2 + k];
        int pos = atomicAdd(&g_cursor[e], 1);
        int slot = g_off[e] + pos;
        g_pair_token[slot] = t;
        g_pair_pos[t * 2 + k] = slot;
    }
}

// ---------------- unified tensor-core grouped GEMM ----------------
// CTA tile 128x128, BK=16, 8 warps (2x4), warp tile 64x32.
// Static smem; fp32 global loads split to bf16 hi/lo in-register; explicit
// ld.shared fragment assembly (no ldmatrix); register-prefetch pipeline.
// IS1: A = gathered x rows (fp32), B = w1 [k=D][e*FF+n];   out: H (gelu, split)
// !IS1: A = H (bf16 pair),         B = w2 [e*FF+k][n=D];   out: g_O (fp32)
#define PITCH 18

template<bool IS1>
__global__ __launch_bounds__(256) void k_gemm_tc(const float* __restrict__ xf,
                                                 const float* __restrict__ Wf) {
    constexpr int KTOT = IS1 ? D_DIM : FFD;
    constexpr int NKC = KTOT / 16;
    __shared__ bf16 Ah[128][PITCH], Al[128][PITCH];
    __shared__ bf16 Bh[128][PITCH], Bl[128][PITCH];
    __shared__ int toks[128];

    const int row0 = blockIdx.y * BM;
    if (row0 >= g_off[E_EXP]) return;
    int e = 0;
    while (row0 >= g_off[e + 1]) e++;
    const int nbase = blockIdx.x * 128;

    const int tid = threadIdx.x;
    const int wid = tid >> 5, lane = tid & 31;
    const int warp_m = wid & 1, warp_n = wid >> 1;

    if (tid < 128) toks[tid] = g_pair_token[row0 + tid];
    __syncthreads();

    // ---- per-thread global-load addressing ----
    // A (IS1): 2 float4 per thread: rows tid>>2 and +64, f4col tid&3
    const int ar1 = tid >> 2, ar2 = ar1 + 64, ac4 = tid & 3;
    const int atok1 = toks[ar1], atok2 = toks[ar2];
    // A (!IS1): 1 uint4 hi + 1 uint4 lo: row tid>>1, half tid&1
    const int hrow = tid >> 1, hhalf = tid & 1;
    // B: 2 float4 per thread: ii = j*256+tid -> krow ii>>5, f4col ii&31
    float4 a_cur[2]; uint4 h_cur[2];
    float4 b_cur[2];

    auto gload = [&](int kc, float4* a_r, uint4* h_r, float4* b_r) {
        if constexpr (IS1) {
            a_r[0] = (atok1 >= 0)
                ? *(const float4*)(xf + (size_t)atok1 * D_DIM + kc * 16 + ac4 * 4)
                : make_float4(0.f, 0.f, 0.f, 0.f);
            a_r[1] = (atok2 >= 0)
                ? *(const float4*)(xf + (size_t)atok2 * D_DIM + kc * 16 + ac4 * 4)
                : make_float4(0.f, 0.f, 0.f, 0.f);
        } else {
            size_t ao = (size_t)(row0 + hrow) * FFD + kc * 16 + hhalf * 8;
            h_r[0] = *(const uint4*)(g_Hhi + ao);
            h_r[1] = *(const uint4*)(g_Hlo + ao);
        }
        #pragma unroll
        for (int j = 0; j < 2; j++) {
            int ii = j * 256 + tid;
            int kr = ii >> 5, n0 = (ii & 31) * 4;
            const float* p = IS1
                ? (Wf + (size_t)(kc * 16 + kr) * W1S + (size_t)e * FFD + nbase + n0)
                : (Wf + ((size_t)e * FFD + kc * 16 + kr) * D_DIM + nbase + n0);
            b_r[j] = *(const float4*)p;
        }
    };

    auto sstore = [&](const float4* a_r, const uint4* h_r, const float4* b_r) {
        if constexpr (IS1) {
            #pragma unroll
            for (int j = 0; j < 2; j++) {
                int r = j ? ar2 : ar1;
                bf16 h0, l0, h1, l1, h2, l2, h3, l3;
                split1(a_r[j].x, h0, l0); split1(a_r[j].y, h1, l1);
                split1(a_r[j].z, h2, l2); split1(a_r[j].w, h3, l3);
                *(uint32_t*)&Ah[r][ac4 * 4]     = pack2(h0, h1);
                *(uint32_t*)&Ah[r][ac4 * 4 + 2] = pack2(h2, h3);
                *(uint32_t*)&Al[r][ac4 * 4]     = pack2(l0, l1);
                *(uint32_t*)&Al[r][ac4 * 4 + 2] = pack2(l2, l3);
            }
        } else {
            uint32_t* dh = (uint32_t*)&Ah[hrow][hhalf * 8];
            uint32_t* dl = (uint32_t*)&Al[hrow][hhalf * 8];
            dh[0] = h_r[0].x; dh[1] = h_r[0].y; dh[2] = h_r[0].z; dh[3] = h_r[0].w;
            dl[0] = h_r[1].x; dl[1] = h_r[1].y; dl[2] = h_r[1].z; dl[3] = h_r[1].w;
        }
        #pragma unroll
        for (int j = 0; j < 2; j++) {
            int ii = j * 256 + tid;
            int kr = ii >> 5, n0 = (ii & 31) * 4;
            float f[4] = { b_r[j].x, b_r[j].y, b_r[j].z, b_r[j].w };
            #pragma unroll
            for (int q = 0; q < 4; q++) {
                bf16 hh, ll;
                split1(f[q], hh, ll);
                Bh[n0 + q][kr] = hh;
                Bl[n0 + q][kr] = ll;
            }
        }
    };

    float acc[4][4][4];
    #pragma unroll
    for (int mt = 0; mt < 4; mt++)
        #pragma unroll
        for (int nt = 0; nt < 4; nt++)
            #pragma unroll
            for (int j = 0; j < 4; j++) acc[mt][nt][j] = 0.0f;

    const int g = lane >> 2, tg = lane & 3;

    gload(0, a_cur, h_cur, b_cur);

    for (int kc = 0; kc < NKC; kc++) {
        sstore(a_cur, h_cur, b_cur);
        float4 a_nxt[2]; uint4 h_nxt[2]; float4 b_nxt[2];
        if (kc + 1 < NKC) gload(kc + 1, a_nxt, h_nxt, b_nxt);
        __syncthreads();

        uint32_t aH[4][4], aL[4][4], bH[4][2], bL[4][2];
        #pragma unroll
        for (int mt = 0; mt < 4; mt++) {
            const int r = warp_m * 64 + mt * 16 + g;
            aH[mt][0] = *(const uint32_t*)&Ah[r][tg * 2];
            aH[mt][1] = *(const uint32_t*)&Ah[r + 8][tg * 2];
            aH[mt][2] = *(const uint32_t*)&Ah[r][8 + tg * 2];
            aH[mt][3] = *(const uint32_t*)&Ah[r + 8][8 + tg * 2];
            aL[mt][0] = *(const uint32_t*)&Al[r][tg * 2];
            aL[mt][1] = *(const uint32_t*)&Al[r + 8][tg * 2];
            aL[mt][2] = *(const uint32_t*)&Al[r][8 + tg * 2];
            aL[mt][3] = *(const uint32_t*)&Al[r + 8][8 + tg * 2];
        }
        #pragma unroll
        for (int nt = 0; nt < 4; nt++) {
            const int br = warp_n * 32 + nt * 8 + g;
            bH[nt][0] = *(const uint32_t*)&Bh[br][tg * 2];
            bH[nt][1] = *(const uint32_t*)&Bh[br][8 + tg * 2];
            bL[nt][0] = *(const uint32_t*)&Bl[br][tg * 2];
            bL[nt][1] = *(const uint32_t*)&Bl[br][8 + tg * 2];
        }
        #pragma unroll
        for (int mt = 0; mt < 4; mt++)
            #pragma unroll
            for (int nt = 0; nt < 4; nt++) {
                float* d = acc[mt][nt];
                mma16816(d, aH[mt], bH[nt]);
                mma16816(d, aH[mt], bL[nt]);
                mma16816(d, aL[mt], bH[nt]);
            }
        __syncthreads();
        a_cur[0] = a_nxt[0]; a_cur[1] = a_nxt[1];
        h_cur[0] = h_nxt[0]; h_cur[1] = h_nxt[1];
        b_cur[0] = b_nxt[0]; b_cur[1] = b_nxt[1];
    }

    // ---- epilogue ----
    #pragma unroll
    for (int mt = 0; mt < 4; mt++) {
        const int r_lo = row0 + warp_m * 64 + mt * 16 + g;
        #pragma unroll
        for (int nt = 0; nt < 4; nt++) {
            const int c = nbase + warp_n * 32 + nt * 8 + tg * 2;
            float* d = acc[mt][nt];
            if constexpr (IS1) {
                float f0 = gelu_exact(d[0]), f1 = gelu_exact(d[1]);
                float f2 = gelu_exact(d[2]), f3 = gelu_exact(d[3]);
                bf16 h0, l0, h1, l1, h2, l2, h3, l3;
                split1(f0, h0, l0); split1(f1, h1, l1);
                split1(f2, h2, l2); split1(f3, h3, l3);
                *(uint32_t*)(g_Hhi + (size_t)r_lo * FFD + c)       = pack2(h0, h1);
                *(uint32_t*)(g_Hlo + (size_t)r_lo * FFD + c)       = pack2(l0, l1);
                *(uint32_t*)(g_Hhi + (size_t)(r_lo + 8) * FFD + c) = pack2(h2, h3);
                *(uint32_t*)(g_Hlo + (size_t)(r_lo + 8) * FFD + c) = pack2(l2, l3);
            } else {
                *(float2*)(g_O + (size_t)r_lo * D_DIM + c)       = make_float2(d[0], d[1]);
                *(float2*)(g_O + (size_t)(r_lo + 8) * D_DIM + c) = make_float2(d[2], d[3]);
            }
        }
    }
}

// ---------------- combine + final scalars ----------------
__global__ void k_combine(float* __restrict__ out) {
    int i = blockIdx.x * 256 + threadIdx.x;
    const int NQ = T_TOK * D_DIM / 4;
    if (i >= NQ) return;
    int t  = i / (D_DIM / 4);
    int d4 = i % (D_DIM / 4);
    int p0 = g_pair_pos[t * 2 + 0], p1 = g_pair_pos[t * 2 + 1];
    float w0 = g_topw[t * 2 + 0], w1 = g_topw[t * 2 + 1];
    float4 o0 = *(const float4*)&g_O[(size_t)p0 * D_DIM + d4 * 4];
    float4 o1 = *(const float4*)&g_O[(size_t)p1 * D_DIM + d4 * 4];
    float4 r;
    r.x = w0 * o0.x + w1 * o1.x;
    r.y = w0 * o0.y + w1 * o1.y;
    r.z = w0 * o0.z + w1 * o1.z;
    r.w = w0 * o0.w + w1 * o1.w;
    ((float4*)out)[i] = r;
}

__global__ void k_final(float* __restrict__ out, int out_size) {
    if (threadIdx.x == 0 && out_size >= T_TOK * D_DIM + 2) {
        float z = g_z_acc / (float)T_TOK;
        float lb = 0.0f;
        for (int e = 0; e < E_EXP; e++) {
            float f_i = (float)g_count[e] / (float)(T_TOK * TOPK);
            float p_i = g_p_acc[e] / (float)T_TOK;
            lb += f_i * p_i;
        }
        lb *= (float)E_EXP;
        out[T_TOK * D_DIM + 0] = z;
        out[T_TOK * D_DIM + 1] = lb;
    }
}

extern "C" void kernel_launch(void* const* d_in, const int* in_sizes, int n_in,
                              void* d_out, int out_size) {
    const float* x  = (const float*)d_in[0];
    const float* rw = (const float*)d_in[1];
    const float* w1 = (const float*)d_in[2];
    const float* w2 = (const float*)d_in[3];
    float* out = (float*)d_out;

    k_init<<<(CAP + 255) / 256, 256>>>();
    k_router<<<T_TOK, 256>>>(x, rw);
    k_scan<<<1, 32>>>();
    k_scatter<<<(T_TOK + 255) / 256, 256>>>();
    k_gemm_tc<true><<<dim3(FFD / 128, NT_ROW), 256>>>(x, w1);
    k_gemm_tc<false><<<dim3(D_DIM / 128, NT_ROW), 256>>>(g_O, w2);
    k_combine<<<(T_TOK * D_DIM / 4 + 255) / 256, 256>>>(out);
    k_final<<<1, 32>>>(out, out_size);
}

// round 14
// speedup vs baseline: 1.5728x; 1.0413x over previous
#include <cuda_runtime.h>
#include <cuda_bf16.h>
#include <math.h>
#include <stdint.h>

typedef __nv_bfloat16 bf16;

#define T_TOK 8192
#define D_DIM 1024
#define E_EXP 8
#define TOPK  2
#define FFD   2048
#define W1S   (FFD * E_EXP)
#define NPAIR (T_TOK * TOPK)
#define BM 128
#define NT_ROW 136
#define CAP (NT_ROW * BM)

// ---------------- static device scratch (~210MB) ----------------
// g_W holds W1T [e*FF+n][D] during GEMM1, then W2T [e*D+n][FF] during GEMM2.
// NOTE: these symbols are referenced ONLY inside device code — never passed
// as kernel-launch arguments (host shadow-symbol trap).
__device__ __align__(16) bf16  g_Whi[(size_t)E_EXP * FFD * D_DIM];
__device__ __align__(16) bf16  g_Wlo[(size_t)E_EXP * FFD * D_DIM];
__device__ __align__(16) bf16  g_Hhi[(size_t)CAP * FFD];
__device__ __align__(16) bf16  g_Hlo[(size_t)CAP * FFD];
__device__ int   g_pair_token[CAP];
__device__ float g_slot_w[CAP];
__device__ int   g_sel[NPAIR];
__device__ float g_topw[NPAIR];
__device__ int   g_count[E_EXP];
__device__ int   g_cursor[E_EXP];
__device__ int   g_off[E_EXP + 1];
__device__ float g_z_acc;
__device__ float g_p_acc[E_EXP];

__device__ __forceinline__ float gelu_exact(float v) {
    return 0.5f * v * (1.0f + erff(v * 0.70710678118654752440f));
}
__device__ __forceinline__ uint32_t pack2(bf16 a, bf16 b) {
    return ((uint32_t)__bfloat16_as_ushort(b) << 16) | (uint32_t)__bfloat16_as_ushort(a);
}
__device__ __forceinline__ void split1(float f, bf16& h, bf16& l) {
    h = __float2bfloat16(f);
    l = __float2bfloat16(f - __bfloat162float(h));
}
__device__ __forceinline__ void mma16816(float* d, const uint32_t* a, const uint32_t* b) {
    asm volatile("mma.sync.aligned.m16n8k16.row.col.f32.bf16.bf16.f32 "
                 "{%0,%1,%2,%3}, {%4,%5,%6,%7}, {%8,%9}, {%0,%1,%2,%3};"
                 : "+f"(d[0]), "+f"(d[1]), "+f"(d[2]), "+f"(d[3])
                 : "r"(a[0]), "r"(a[1]), "r"(a[2]), "r"(a[3]), "r"(b[0]), "r"(b[1]));
}
__device__ __forceinline__ void redadd(float* p, float v) {
    asm volatile("red.global.add.f32 [%0], %1;" :: "l"(p), "f"(v) : "memory");
}

// ---------------- init / zero ----------------
__global__ void k_init() {
    int i = blockIdx.x * 256 + threadIdx.x;
    if (i < CAP) g_pair_token[i] = -1;
    if (i < E_EXP) { g_count[i] = 0; g_cursor[i] = 0; g_p_acc[i] = 0.0f; }
    if (i == 0) g_z_acc = 0.0f;
}
__global__ void k_zero(float* __restrict__ out, int n) {
    int i = blockIdx.x * 256 + threadIdx.x;
    if (i < n) out[i] = 0.0f;
}

// ---------------- router ----------------
__global__ __launch_bounds__(256) void k_router(const float* __restrict__ x,
                                                const float* __restrict__ rw) {
    __shared__ float xs[D_DIM];
    __shared__ float logits[E_EXP];
    int t = blockIdx.x;
    const float* xr = x + (size_t)t * D_DIM;
    for (int i = threadIdx.x; i < D_DIM; i += 256) xs[i] = xr[i];
    __syncthreads();
    int w = threadIdx.x >> 5, lane = threadIdx.x & 31;
    float s = 0.0f;
    const float* we = rw + (size_t)w * D_DIM;
    for (int i = lane; i < D_DIM; i += 32) s += xs[i] * we[i];
    for (int o = 16; o; o >>= 1) s += __shfl_xor_sync(0xFFFFFFFFu, s, o);
    if (lane == 0) logits[w] = s;
    __syncthreads();
    if (threadIdx.x == 0) {
        float mx = logits[0];
        for (int e = 1; e < E_EXP; e++) mx = fmaxf(mx, logits[e]);
        float p[E_EXP]; float se = 0.0f;
        for (int e = 0; e < E_EXP; e++) { p[e] = expf(logits[e] - mx); se += p[e]; }
        float inv = 1.0f / se;
        for (int e = 0; e < E_EXP; e++) p[e] *= inv;
        float lse = mx + logf(se);
        atomicAdd(&g_z_acc, lse * lse);
        for (int e = 0; e < E_EXP; e++) atomicAdd(&g_p_acc[e], p[e]);
        int i0 = 0;
        for (int e = 1; e < E_EXP; e++) if (p[e] > p[i0]) i0 = e;
        int i1 = -1;
        for (int e = 0; e < E_EXP; e++) {
            if (e == i0) continue;
            if (i1 < 0 || p[e] > p[i1]) i1 = e;
        }
        float s2 = p[i0] + p[i1];
        g_sel[t * 2 + 0] = i0; g_sel[t * 2 + 1] = i1;
        g_topw[t * 2 + 0] = p[i0] / s2; g_topw[t * 2 + 1] = p[i1] / s2;
        atomicAdd(&g_count[i0], 1); atomicAdd(&g_count[i1], 1);
    }
}

__global__ void k_scan() {
    if (threadIdx.x == 0) {
        int off = 0;
        for (int e = 0; e < E_EXP; e++) {
            g_off[e] = off;
            off += ((g_count[e] + BM - 1) / BM) * BM;
        }
        g_off[E_EXP] = off;
    }
}

__global__ void k_scatter() {
    int t = blockIdx.x * 256 + threadIdx.x;
    if (t >= T_TOK) return;
    #pragma unroll
    for (int k = 0; k < TOPK; k++) {
        int e = g_sel[t * 2 + k];
        int pos = atomicAdd(&g_cursor[e], 1);
        int slot = g_off[e] + pos;
        g_pair_token[slot] = t;
        g_slot_w[slot] = g_topw[t * 2 + k];
    }
}

// ---------------- weight transpose+split -> g_Whi/g_Wlo (direct symbols) ----------------
// W1MODE: src = w1 [D][W1S], dst [W1S][D] (one z block).
// else:   src = w2 [e][FFD][D], dst [e][D][FFD] per z = expert.
template<bool W1MODE>
__global__ __launch_bounds__(256) void k_tsplit(const float* __restrict__ src) {
    constexpr int R = W1MODE ? D_DIM : FFD;
    constexpr int C = W1MODE ? W1S : D_DIM;
    __shared__ float ts[32][33];
    size_t zoff = (size_t)blockIdx.z * R * C;
    int c0 = blockIdx.x * 32, r0 = blockIdx.y * 32;
    int tx = threadIdx.x & 31, ty = threadIdx.x >> 5;
    #pragma unroll
    for (int j = 0; j < 4; j++)
        ts[ty + j * 8][tx] = src[zoff + (size_t)(r0 + ty + j * 8) * C + c0 + tx];
    __syncthreads();
    #pragma unroll
    for (int j = 0; j < 4; j++) {
        float v = ts[tx][ty + j * 8];
        bf16 hh, ll;
        split1(v, hh, ll);
        size_t o = zoff + (size_t)(c0 + ty + j * 8) * R + r0 + tx;
        g_Whi[o] = hh; g_Wlo[o] = ll;
    }
}

// ---------------- tensor-core grouped GEMM ----------------
// CTA 128x128, BK=32, 8 warps (2x4), warp tile 64x32, PITCH 40 bf16 (80B rows).
// IS1: A = x rows via token indirection (split in-kernel), B = W1T; out: H (gelu+split).
// !IS1: A = H (pre-split), B = W2T; epilogue: weighted red.add into out[token].
#define PITCH 40

template<bool IS1>
__global__ __launch_bounds__(256) void k_gemm(const float* __restrict__ xf,
                                              float* __restrict__ outp) {
    constexpr int KTOT = IS1 ? D_DIM : FFD;
    constexpr int NBT  = IS1 ? FFD : D_DIM;
    constexpr int NKC  = KTOT / 32;
    __shared__ bf16 Ah[128][PITCH], Al[128][PITCH];
    __shared__ bf16 Bh[128][PITCH], Bl[128][PITCH];
    __shared__ int   toks[128];
    __shared__ float ws[128];

    const int row0 = blockIdx.y * BM;
    if (row0 >= g_off[E_EXP]) return;
    int e = 0;
    while (row0 >= g_off[e + 1]) e++;
    const int nbase = blockIdx.x * 128;

    const int tid = threadIdx.x;
    const int wid = tid >> 5, lane = tid & 31;
    const int warp_m = wid & 1, warp_n = wid >> 1;

    if (tid < 128) {
        toks[tid] = g_pair_token[row0 + tid];
        ws[tid]   = g_slot_w[row0 + tid];
    }
    __syncthreads();

    // ---- global load addressing: thread owns row lr, 16-element k-half ----
    const int lr = tid >> 1, half = tid & 1;
    const float* xrow = nullptr;
    const bf16 *pAh = nullptr, *pAl = nullptr;
    if constexpr (IS1) {
        int tk = toks[lr];
        xrow = (tk >= 0) ? xf + (size_t)tk * D_DIM + half * 16 : nullptr;
    } else {
        pAh = g_Hhi + (size_t)(row0 + lr) * FFD + half * 16;
        pAl = g_Hlo + (size_t)(row0 + lr) * FFD + half * 16;
    }
    const bf16* pBh = g_Whi + (size_t)(e * NBT + nbase + lr) * KTOT + half * 16;
    const bf16* pBl = g_Wlo + (size_t)(e * NBT + nbase + lr) * KTOT + half * 16;

    float4 fa[4]; uint4 ua[2], ul[2], ub[2], uq[2];
    auto gload = [&](int kc, float4* f, uint4* a, uint4* l, uint4* b, uint4* q) {
        if constexpr (IS1) {
            if (xrow) {
                #pragma unroll
                for (int i = 0; i < 4; i++) f[i] = *(const float4*)(xrow + kc * 32 + i * 4);
            } else {
                #pragma unroll
                for (int i = 0; i < 4; i++) f[i] = make_float4(0.f, 0.f, 0.f, 0.f);
            }
        } else {
            a[0] = *(const uint4*)(pAh + kc * 32);
            a[1] = *(const uint4*)(pAh + kc * 32 + 8);
            l[0] = *(const uint4*)(pAl + kc * 32);
            l[1] = *(const uint4*)(pAl + kc * 32 + 8);
        }
        b[0] = *(const uint4*)(pBh + kc * 32);
        b[1] = *(const uint4*)(pBh + kc * 32 + 8);
        q[0] = *(const uint4*)(pBl + kc * 32);
        q[1] = *(const uint4*)(pBl + kc * 32 + 8);
    };
    auto sstore = [&](const float4* f, const uint4* a, const uint4* l,
                      const uint4* b, const uint4* q) {
        if constexpr (IS1) {
            uint32_t ph[8], pl[8];
            #pragma unroll
            for (int i = 0; i < 4; i++) {
                bf16 h0, l0, h1, l1, h2, l2, h3, l3;
                split1(f[i].x, h0, l0); split1(f[i].y, h1, l1);
                split1(f[i].z, h2, l2); split1(f[i].w, h3, l3);
                ph[i * 2]     = pack2(h0, h1); ph[i * 2 + 1] = pack2(h2, h3);
                pl[i * 2]     = pack2(l0, l1); pl[i * 2 + 1] = pack2(l2, l3);
            }
            *(uint4*)&Ah[lr][half * 16]     = ((uint4*)ph)[0];
            *(uint4*)&Ah[lr][half * 16 + 8] = ((uint4*)ph)[1];
            *(uint4*)&Al[lr][half * 16]     = ((uint4*)pl)[0];
            *(uint4*)&Al[lr][half * 16 + 8] = ((uint4*)pl)[1];
        } else {
            *(uint4*)&Ah[lr][half * 16]     = a[0];
            *(uint4*)&Ah[lr][half * 16 + 8] = a[1];
            *(uint4*)&Al[lr][half * 16]     = l[0];
            *(uint4*)&Al[lr][half * 16 + 8] = l[1];
        }
        *(uint4*)&Bh[lr][half * 16]     = b[0];
        *(uint4*)&Bh[lr][half * 16 + 8] = b[1];
        *(uint4*)&Bl[lr][half * 16]     = q[0];
        *(uint4*)&Bl[lr][half * 16 + 8] = q[1];
    };

    float acc[4][4][4];
    #pragma unroll
    for (int mt = 0; mt < 4; mt++)
        #pragma unroll
        for (int nt = 0; nt < 4; nt++)
            #pragma unroll
            for (int j = 0; j < 4; j++) acc[mt][nt][j] = 0.0f;

    const int g = lane >> 2, tg = lane & 3;

    gload(0, fa, ua, ul, ub, uq);

    for (int kc = 0; kc < NKC; kc++) {
        sstore(fa, ua, ul, ub, uq);
        float4 nf[4]; uint4 na[2], nl[2], nb[2], nq[2];
        if (kc + 1 < NKC) gload(kc + 1, nf, na, nl, nb, nq);
        __syncthreads();

        #pragma unroll
        for (int ks = 0; ks < 2; ks++) {
            const int cb = ks * 16;
            uint32_t aH[4][4], aL[4][4], bH[4][2], bL[4][2];
            #pragma unroll
            for (int mt = 0; mt < 4; mt++) {
                const int r = warp_m * 64 + mt * 16 + g;
                aH[mt][0] = *(const uint32_t*)&Ah[r][cb + tg * 2];
                aH[mt][1] = *(const uint32_t*)&Ah[r + 8][cb + tg * 2];
                aH[mt][2] = *(const uint32_t*)&Ah[r][cb + 8 + tg * 2];
                aH[mt][3] = *(const uint32_t*)&Ah[r + 8][cb + 8 + tg * 2];
                aL[mt][0] = *(const uint32_t*)&Al[r][cb + tg * 2];
                aL[mt][1] = *(const uint32_t*)&Al[r + 8][cb + tg * 2];
                aL[mt][2] = *(const uint32_t*)&Al[r][cb + 8 + tg * 2];
                aL[mt][3] = *(const uint32_t*)&Al[r + 8][cb + 8 + tg * 2];
            }
            #pragma unroll
            for (int nt = 0; nt < 4; nt++) {
                const int br = warp_n * 32 + nt * 8 + g;
                bH[nt][0] = *(const uint32_t*)&Bh[br][cb + tg * 2];
                bH[nt][1] = *(const uint32_t*)&Bh[br][cb + 8 + tg * 2];
                bL[nt][0] = *(const uint32_t*)&Bl[br][cb + tg * 2];
                bL[nt][1] = *(const uint32_t*)&Bl[br][cb + 8 + tg * 2];
            }
            #pragma unroll
            for (int mt = 0; mt < 4; mt++)
                #pragma unroll
                for (int nt = 0; nt < 4; nt++) {
                    float* d = acc[mt][nt];
                    mma16816(d, aH[mt], bH[nt]);
                    mma16816(d, aH[mt], bL[nt]);
                    mma16816(d, aL[mt], bH[nt]);
                }
        }
        __syncthreads();
        if (kc + 1 < NKC) {
            #pragma unroll
            for (int i = 0; i < 4; i++) fa[i] = nf[i];
            ua[0] = na[0]; ua[1] = na[1]; ul[0] = nl[0]; ul[1] = nl[1];
            ub[0] = nb[0]; ub[1] = nb[1]; uq[0] = nq[0]; uq[1] = nq[1];
        }
    }

    // ---- epilogue ----
    #pragma unroll
    for (int mt = 0; mt < 4; mt++) {
        const int rr = warp_m * 64 + mt * 16 + g;       // local row (0..127)
        #pragma unroll
        for (int nt = 0; nt < 4; nt++) {
            const int c = nbase + warp_n * 32 + nt * 8 + tg * 2;
            float* d = acc[mt][nt];
            if constexpr (IS1) {
                const int r_lo = row0 + rr;
                float f0 = gelu_exact(d[0]), f1 = gelu_exact(d[1]);
                float f2 = gelu_exact(d[2]), f3 = gelu_exact(d[3]);
                bf16 h0, l0, h1, l1, h2, l2, h3, l3;
                split1(f0, h0, l0); split1(f1, h1, l1);
                split1(f2, h2, l2); split1(f3, h3, l3);
                *(uint32_t*)(g_Hhi + (size_t)r_lo * FFD + c)       = pack2(h0, h1);
                *(uint32_t*)(g_Hlo + (size_t)r_lo * FFD + c)       = pack2(l0, l1);
                *(uint32_t*)(g_Hhi + (size_t)(r_lo + 8) * FFD + c) = pack2(h2, h3);
                *(uint32_t*)(g_Hlo + (size_t)(r_lo + 8) * FFD + c) = pack2(l2, l3);
            } else {
                int t0 = toks[rr], t1 = toks[rr + 8];
                float w0 = ws[rr], w1 = ws[rr + 8];
                if (t0 >= 0) {
                    float* p = outp + (size_t)t0 * D_DIM + c;
                    redadd(p, w0 * d[0]); redadd(p + 1, w0 * d[1]);
                }
                if (t1 >= 0) {
                    float* p = outp + (size_t)t1 * D_DIM + c;
                    redadd(p, w1 * d[2]); redadd(p + 1, w1 * d[3]);
                }
            }
        }
    }
}

// ---------------- final scalars ----------------
__global__ void k_final(float* __restrict__ out, int out_size) {
    if (threadIdx.x == 0 && out_size >= T_TOK * D_DIM + 2) {
        float z = g_z_acc / (float)T_TOK;
        float lb = 0.0f;
        for (int e = 0; e < E_EXP; e++) {
            float f_i = (float)g_count[e] / (float)(T_TOK * TOPK);
            float p_i = g_p_acc[e] / (float)T_TOK;
            lb += f_i * p_i;
        }
        lb *= (float)E_EXP;
        out[T_TOK * D_DIM + 0] = z;
        out[T_TOK * D_DIM + 1] = lb;
    }
}

extern "C" void kernel_launch(void* const* d_in, const int* in_sizes, int n_in,
                              void* d_out, int out_size) {
    const float* x  = (const float*)d_in[0];
    const float* rw = (const float*)d_in[1];
    const float* w1 = (const float*)d_in[2];
    const float* w2 = (const float*)d_in[3];
    float* out = (float*)d_out;

    const int nout = T_TOK * D_DIM + 2;
    k_zero<<<(nout + 255) / 256, 256>>>(out, out_size < nout ? out_size : nout);
    k_init<<<(CAP + 255) / 256, 256>>>();
    k_router<<<T_TOK, 256>>>(x, rw);
    k_scan<<<1, 32>>>();
    k_scatter<<<(T_TOK + 255) / 256, 256>>>();
    // W1T: [D][E*FF] -> [e*FF+n][D]
    k_tsplit<true><<<dim3(W1S / 32, D_DIM / 32, 1), 256>>>(w1);
    k_gemm<true><<<dim3(FFD / 128, NT_ROW), 256>>>(x, out);
    // W2T: per-expert [FF][D] -> [e*D+n][FF]  (reuses the same buffer)
    k_tsplit<false><<<dim3(D_DIM / 32, FFD / 32, E_EXP), 256>>>(w2);
    k_gemm<false><<<dim3(D_DIM / 128, NT_ROW), 256>>>(x, out);
    k_final<<<1, 32>>>(out, out_size);
}

// round 16
// speedup vs baseline: 1.8497x; 1.1761x over previous
#include <cuda_runtime.h>
#include <cuda_bf16.h>
#include <math.h>
#include <stdint.h>

typedef __nv_bfloat16 bf16;

#define T_TOK 8192
#define D_DIM 1024
#define E_EXP 8
#define TOPK  2
#define FFD   2048
#define W1S   (FFD * E_EXP)
#define NPAIR (T_TOK * TOPK)
#define BM 128
#define NT_ROW 136
#define CAP (NT_ROW * BM)

// ---------------- static device scratch (~210MB) ----------------
// Referenced ONLY inside device code — never passed as kernel arguments
// (host shadow-symbol trap).
__device__ __align__(16) bf16  g_Whi[(size_t)E_EXP * FFD * D_DIM];
__device__ __align__(16) bf16  g_Wlo[(size_t)E_EXP * FFD * D_DIM];
__device__ __align__(16) bf16  g_Hhi[(size_t)CAP * FFD];
__device__ __align__(16) bf16  g_Hlo[(size_t)CAP * FFD];
__device__ int   g_pair_token[CAP];
__device__ float g_slot_w[CAP];
__device__ int   g_sel[NPAIR];
__device__ float g_topw[NPAIR];
__device__ int   g_count[E_EXP];
__device__ int   g_cursor[E_EXP];
__device__ int   g_off[E_EXP + 1];
__device__ float g_z_acc;
__device__ float g_p_acc[E_EXP];

__device__ __forceinline__ float gelu_exact(float v) {
    return 0.5f * v * (1.0f + erff(v * 0.70710678118654752440f));
}
__device__ __forceinline__ uint32_t pack2(bf16 a, bf16 b) {
    return ((uint32_t)__bfloat16_as_ushort(b) << 16) | (uint32_t)__bfloat16_as_ushort(a);
}
__device__ __forceinline__ void split1(float f, bf16& h, bf16& l) {
    h = __float2bfloat16(f);
    l = __float2bfloat16(f - __bfloat162float(h));
}
__device__ __forceinline__ uint32_t smem_u32(const void* p) {
    uint32_t a;
    asm("{ .reg .u64 t; cvta.to.shared.u64 t, %1; cvt.u32.u64 %0, t; }" : "=r"(a) : "l"(p));
    return a;
}
__device__ __forceinline__ void ldsm4(uint32_t* r, uint32_t addr) {
    asm volatile("ldmatrix.sync.aligned.m8n8.x4.shared.b16 {%0,%1,%2,%3}, [%4];"
                 : "=r"(r[0]), "=r"(r[1]), "=r"(r[2]), "=r"(r[3]) : "r"(addr));
}
__device__ __forceinline__ void mma16816(float* d, const uint32_t* a, const uint32_t* b) {
    asm volatile("mma.sync.aligned.m16n8k16.row.col.f32.bf16.bf16.f32 "
                 "{%0,%1,%2,%3}, {%4,%5,%6,%7}, {%8,%9}, {%0,%1,%2,%3};"
                 : "+f"(d[0]), "+f"(d[1]), "+f"(d[2]), "+f"(d[3])
                 : "r"(a[0]), "r"(a[1]), "r"(a[2]), "r"(a[3]), "r"(b[0]), "r"(b[1]));
}
__device__ __forceinline__ void redadd(float* p, float v) {
    asm volatile("red.global.add.f32 [%0], %1;" :: "l"(p), "f"(v) : "memory");
}

// ---------------- init / zero ----------------
__global__ void k_init() {
    int i = blockIdx.x * 256 + threadIdx.x;
    if (i < CAP) g_pair_token[i] = -1;
    if (i < E_EXP) { g_count[i] = 0; g_cursor[i] = 0; g_p_acc[i] = 0.0f; }
    if (i == 0) g_z_acc = 0.0f;
}
__global__ void k_zero(float* __restrict__ out, int n) {
    int i = blockIdx.x * 256 + threadIdx.x;
    if (i < n) out[i] = 0.0f;
}

// ---------------- router ----------------
__global__ __launch_bounds__(256) void k_router(const float* __restrict__ x,
                                                const float* __restrict__ rw) {
    __shared__ float xs[D_DIM];
    __shared__ float logits[E_EXP];
    int t = blockIdx.x;
    const float* xr = x + (size_t)t * D_DIM;
    for (int i = threadIdx.x; i < D_DIM; i += 256) xs[i] = xr[i];
    __syncthreads();
    int w = threadIdx.x >> 5, lane = threadIdx.x & 31;
    float s = 0.0f;
    const float* we = rw + (size_t)w * D_DIM;
    for (int i = lane; i < D_DIM; i += 32) s += xs[i] * we[i];
    for (int o = 16; o; o >>= 1) s += __shfl_xor_sync(0xFFFFFFFFu, s, o);
    if (lane == 0) logits[w] = s;
    __syncthreads();
    if (threadIdx.x == 0) {
        float mx = logits[0];
        for (int e = 1; e < E_EXP; e++) mx = fmaxf(mx, logits[e]);
        float p[E_EXP]; float se = 0.0f;
        for (int e = 0; e < E_EXP; e++) { p[e] = expf(logits[e] - mx); se += p[e]; }
        float inv = 1.0f / se;
        for (int e = 0; e < E_EXP; e++) p[e] *= inv;
        float lse = mx + logf(se);
        atomicAdd(&g_z_acc, lse * lse);
        for (int e = 0; e < E_EXP; e++) atomicAdd(&g_p_acc[e], p[e]);
        int i0 = 0;
        for (int e = 1; e < E_EXP; e++) if (p[e] > p[i0]) i0 = e;
        int i1 = -1;
        for (int e = 0; e < E_EXP; e++) {
            if (e == i0) continue;
            if (i1 < 0 || p[e] > p[i1]) i1 = e;
        }
        float s2 = p[i0] + p[i1];
        g_sel[t * 2 + 0] = i0; g_sel[t * 2 + 1] = i1;
        g_topw[t * 2 + 0] = p[i0] / s2; g_topw[t * 2 + 1] = p[i1] / s2;
        atomicAdd(&g_count[i0], 1); atomicAdd(&g_count[i1], 1);
    }
}

__global__ void k_scan() {
    if (threadIdx.x == 0) {
        int off = 0;
        for (int e = 0; e < E_EXP; e++) {
            g_off[e] = off;
            off += ((g_count[e] + BM - 1) / BM) * BM;
        }
        g_off[E_EXP] = off;
    }
}

__global__ void k_scatter() {
    int t = blockIdx.x * 256 + threadIdx.x;
    if (t >= T_TOK) return;
    #pragma unroll
    for (int k = 0; k < TOPK; k++) {
        int e = g_sel[t * 2 + k];
        int pos = atomicAdd(&g_cursor[e], 1);
        int slot = g_off[e] + pos;
        g_pair_token[slot] = t;
        g_slot_w[slot] = g_topw[t * 2 + k];
    }
}

// ---------------- weight transpose+split -> g_Whi/g_Wlo ----------------
template<bool W1MODE>
__global__ __launch_bounds__(256) void k_tsplit(const float* __restrict__ src) {
    constexpr int R = W1MODE ? D_DIM : FFD;
    constexpr int C = W1MODE ? W1S : D_DIM;
    __shared__ float ts[32][33];
    size_t zoff = (size_t)blockIdx.z * R * C;
    int c0 = blockIdx.x * 32, r0 = blockIdx.y * 32;
    int tx = threadIdx.x & 31, ty = threadIdx.x >> 5;
    #pragma unroll
    for (int j = 0; j < 4; j++)
        ts[ty + j * 8][tx] = src[zoff + (size_t)(r0 + ty + j * 8) * C + c0 + tx];
    __syncthreads();
    #pragma unroll
    for (int j = 0; j < 4; j++) {
        float v = ts[tx][ty + j * 8];
        bf16 hh, ll;
        split1(v, hh, ll);
        size_t o = zoff + (size_t)(c0 + ty + j * 8) * R + r0 + tx;
        g_Whi[o] = hh; g_Wlo[o] = ll;
    }
}

// ---------------- tensor-core grouped GEMM ----------------
// CTA 128x128, BK=32, 8 warps (2x4), warp tile 64x32, PITCH 40 bf16 (80B rows).
// Fragments via ldmatrix.x4 (conflict-free on 80B-pitch rows).
#define PITCH 40

template<bool IS1>
__global__ __launch_bounds__(256) void k_gemm(const float* __restrict__ xf,
                                              float* __restrict__ outp) {
    constexpr int KTOT = IS1 ? D_DIM : FFD;
    constexpr int NBT  = IS1 ? FFD : D_DIM;
    constexpr int NKC  = KTOT / 32;
    __shared__ bf16 Ah[128][PITCH], Al[128][PITCH];
    __shared__ bf16 Bh[128][PITCH], Bl[128][PITCH];
    __shared__ int   toks[128];
    __shared__ float ws[128];

    const int row0 = blockIdx.y * BM;
    if (row0 >= g_off[E_EXP]) return;
    int e = 0;
    while (row0 >= g_off[e + 1]) e++;
    const int nbase = blockIdx.x * 128;

    const int tid = threadIdx.x;
    const int wid = tid >> 5, lane = tid & 31;
    const int warp_m = wid & 1, warp_n = wid >> 1;

    if (tid < 128) {
        toks[tid] = g_pair_token[row0 + tid];
        ws[tid]   = g_slot_w[row0 + tid];
    }
    __syncthreads();

    // ---- global load addressing: thread owns row lr, 16-element k-half ----
    const int lr = tid >> 1, half = tid & 1;
    const float* xrow = nullptr;
    const bf16 *pAh = nullptr, *pAl = nullptr;
    if constexpr (IS1) {
        int tk = toks[lr];
        xrow = (tk >= 0) ? xf + (size_t)tk * D_DIM + half * 16 : nullptr;
    } else {
        pAh = g_Hhi + (size_t)(row0 + lr) * FFD + half * 16;
        pAl = g_Hlo + (size_t)(row0 + lr) * FFD + half * 16;
    }
    const bf16* pBh = g_Whi + (size_t)(e * NBT + nbase + lr) * KTOT + half * 16;
    const bf16* pBl = g_Wlo + (size_t)(e * NBT + nbase + lr) * KTOT + half * 16;

    float4 fa[4]; uint4 ua[2], ul[2], ub[2], uq[2];
    auto gload = [&](int kc, float4* f, uint4* a, uint4* l, uint4* b, uint4* q) {
        if constexpr (IS1) {
            if (xrow) {
                #pragma unroll
                for (int i = 0; i < 4; i++) f[i] = *(const float4*)(xrow + kc * 32 + i * 4);
            } else {
                #pragma unroll
                for (int i = 0; i < 4; i++) f[i] = make_float4(0.f, 0.f, 0.f, 0.f);
            }
        } else {
            a[0] = *(const uint4*)(pAh + kc * 32);
            a[1] = *(const uint4*)(pAh + kc * 32 + 8);
            l[0] = *(const uint4*)(pAl + kc * 32);
            l[1] = *(const uint4*)(pAl + kc * 32 + 8);
        }
        b[0] = *(const uint4*)(pBh + kc * 32);
        b[1] = *(const uint4*)(pBh + kc * 32 + 8);
        q[0] = *(const uint4*)(pBl + kc * 32);
        q[1] = *(const uint4*)(pBl + kc * 32 + 8);
    };
    auto sstore = [&](const float4* f, const uint4* a, const uint4* l,
                      const uint4* b, const uint4* q) {
        if constexpr (IS1) {
            uint32_t ph[8], pl[8];
            #pragma unroll
            for (int i = 0; i < 4; i++) {
                bf16 h0, l0, h1, l1, h2, l2, h3, l3;
                split1(f[i].x, h0, l0); split1(f[i].y, h1, l1);
                split1(f[i].z, h2, l2); split1(f[i].w, h3, l3);
                ph[i * 2]     = pack2(h0, h1); ph[i * 2 + 1] = pack2(h2, h3);
                pl[i * 2]     = pack2(l0, l1); pl[i * 2 + 1] = pack2(l2, l3);
            }
            *(uint4*)&Ah[lr][half * 16]     = ((uint4*)ph)[0];
            *(uint4*)&Ah[lr][half * 16 + 8] = ((uint4*)ph)[1];
            *(uint4*)&Al[lr][half * 16]     = ((uint4*)pl)[0];
            *(uint4*)&Al[lr][half * 16 + 8] = ((uint4*)pl)[1];
        } else {
            *(uint4*)&Ah[lr][half * 16]     = a[0];
            *(uint4*)&Ah[lr][half * 16 + 8] = a[1];
            *(uint4*)&Al[lr][half * 16]     = l[0];
            *(uint4*)&Al[lr][half * 16 + 8] = l[1];
        }
        *(uint4*)&Bh[lr][half * 16]     = b[0];
        *(uint4*)&Bh[lr][half * 16 + 8] = b[1];
        *(uint4*)&Bl[lr][half * 16]     = q[0];
        *(uint4*)&Bl[lr][half * 16 + 8] = q[1];
    };

    float acc[4][4][4];
    #pragma unroll
    for (int mt = 0; mt < 4; mt++)
        #pragma unroll
        for (int nt = 0; nt < 4; nt++)
            #pragma unroll
            for (int j = 0; j < 4; j++) acc[mt][nt][j] = 0.0f;

    const int g = lane >> 2, tg = lane & 3;

    // ---- ldmatrix per-thread addressing ----
    // A: rows (lane&15), k-half (lane>>4)*8 elements
    const int a_row = warp_m * 64 + (lane & 15);
    const int a_col = (lane >> 4) * 8;
    // B: m8 = lane>>3: matrices {rows+0,k0}, {rows+0,k1}, {rows+8,k0}, {rows+8,k1}
    const int m8 = lane >> 3, r8 = lane & 7;
    const int b_row = warp_n * 32 + ((m8 >> 1) & 1) * 8 + r8;
    const int b_col = (m8 & 1) * 8;
    const uint32_t sAh = smem_u32(&Ah[0][0]), sAl = smem_u32(&Al[0][0]);
    const uint32_t sBh = smem_u32(&Bh[0][0]), sBl = smem_u32(&Bl[0][0]);

    gload(0, fa, ua, ul, ub, uq);

    for (int kc = 0; kc < NKC; kc++) {
        sstore(fa, ua, ul, ub, uq);
        float4 nf[4]; uint4 na[2], nl[2], nb[2], nq[2];
        if (kc + 1 < NKC) gload(kc + 1, nf, na, nl, nb, nq);
        __syncthreads();

        #pragma unroll
        for (int ks = 0; ks < 2; ks++) {
            const int cb = ks * 16;
            uint32_t aH[4][4], aL[4][4], bH[2][4], bL[2][4];
            #pragma unroll
            for (int mt = 0; mt < 4; mt++) {
                uint32_t off = (uint32_t)(((a_row + mt * 16) * PITCH + cb + a_col) * 2);
                ldsm4(aH[mt], sAh + off);
                ldsm4(aL[mt], sAl + off);
            }
            #pragma unroll
            for (int p = 0; p < 2; p++) {
                uint32_t off = (uint32_t)(((b_row + p * 16) * PITCH + cb + b_col) * 2);
                ldsm4(bH[p], sBh + off);
                ldsm4(bL[p], sBl + off);
            }
            #pragma unroll
            for (int mt = 0; mt < 4; mt++)
                #pragma unroll
                for (int p = 0; p < 2; p++)
                    #pragma unroll
                    for (int sub = 0; sub < 2; sub++) {
                        float* d = acc[mt][p * 2 + sub];
                        mma16816(d, aH[mt], &bH[p][sub * 2]);
                        mma16816(d, aH[mt], &bL[p][sub * 2]);
                        mma16816(d, aL[mt], &bH[p][sub * 2]);
                    }
        }
        __syncthreads();
        if (kc + 1 < NKC) {
            #pragma unroll
            for (int i = 0; i < 4; i++) fa[i] = nf[i];
            ua[0] = na[0]; ua[1] = na[1]; ul[0] = nl[0]; ul[1] = nl[1];
            ub[0] = nb[0]; ub[1] = nb[1]; uq[0] = nq[0]; uq[1] = nq[1];
        }
    }

    // ---- epilogue ----
    #pragma unroll
    for (int mt = 0; mt < 4; mt++) {
        const int rr = warp_m * 64 + mt * 16 + g;       // local row (0..127)
        #pragma unroll
        for (int nt = 0; nt < 4; nt++) {
            const int c = nbase + warp_n * 32 + nt * 8 + tg * 2;
            float* d = acc[mt][nt];
            if constexpr (IS1) {
                const int r_lo = row0 + rr;
                float f0 = gelu_exact(d[0]), f1 = gelu_exact(d[1]);
                float f2 = gelu_exact(d[2]), f3 = gelu_exact(d[3]);
                bf16 h0, l0, h1, l1, h2, l2, h3, l3;
                split1(f0, h0, l0); split1(f1, h1, l1);
                split1(f2, h2, l2); split1(f3, h3, l3);
                *(uint32_t*)(g_Hhi + (size_t)r_lo * FFD + c)       = pack2(h0, h1);
                *(uint32_t*)(g_Hlo + (size_t)r_lo * FFD + c)       = pack2(l0, l1);
                *(uint32_t*)(g_Hhi + (size_t)(r_lo + 8) * FFD + c) = pack2(h2, h3);
                *(uint32_t*)(g_Hlo + (size_t)(r_lo + 8) * FFD + c) = pack2(l2, l3);
            } else {
                int t0 = toks[rr], t1 = toks[rr + 8];
                float w0 = ws[rr], w1 = ws[rr + 8];
                if (t0 >= 0) {
                    float* p = outp + (size_t)t0 * D_DIM + c;
                    redadd(p, w0 * d[0]); redadd(p + 1, w0 * d[1]);
                }
                if (t1 >= 0) {
                    float* p = outp + (size_t)t1 * D_DIM + c;
                    redadd(p, w1 * d[2]); redadd(p + 1, w1 * d[3]);
                }
            }
        }
    }
}

// ---------------- final scalars ----------------
__global__ void k_final(float* __restrict__ out, int out_size) {
    if (threadIdx.x == 0 && out_size >= T_TOK * D_DIM + 2) {
        float z = g_z_acc / (float)T_TOK;
        float lb = 0.0f;
        for (int e = 0; e < E_EXP; e++) {
            float f_i = (float)g_count[e] / (float)(T_TOK * TOPK);
            float p_i = g_p_acc[e] / (float)T_TOK;
            lb += f_i * p_i;
        }
        lb *= (float)E_EXP;
        out[T_TOK * D_DIM + 0] = z;
        out[T_TOK * D_DIM + 1] = lb;
    }
}

extern "C" void kernel_launch(void* const* d_in, const int* in_sizes, int n_in,
                              void* d_out, int out_size) {
    const float* x  = (const float*)d_in[0];
    const float* rw = (const float*)d_in[1];
    const float* w1 = (const float*)d_in[2];
    const float* w2 = (const float*)d_in[3];
    float* out = (float*)d_out;

    const int nout = T_TOK * D_DIM + 2;
    k_zero<<<(nout + 255) / 256, 256>>>(out, out_size < nout ? out_size : nout);
    k_init<<<(CAP + 255) / 256, 256>>>();
    k_router<<<T_TOK, 256>>>(x, rw);
    k_scan<<<1, 32>>>();
    k_scatter<<<(T_TOK + 255) / 256, 256>>>();
    // W1T: [D][E*FF] -> [e*FF+n][D]
    k_tsplit<true><<<dim3(W1S / 32, D_DIM / 32, 1), 256>>>(w1);
    k_gemm<true><<<dim3(FFD / 128, NT_ROW), 256>>>(x, out);
    // W2T: per-expert [FF][D] -> [e*D+n][FF]  (reuses the same buffer)
    k_tsplit<false><<<dim3(D_DIM / 32, FFD / 32, E_EXP), 256>>>(w2);
    k_gemm<false><<<dim3(D_DIM / 128, NT_ROW), 256>>>(x, out);
    k_final<<<1, 32>>>(out, out_size);
}